// round 1
// baseline (speedup 1.0000x reference)
#include <cuda_runtime.h>
#include <math.h>

#define Hdim 1024
#define Bdim 256
#define Tdim 64
#define Odim 8192

// Scratch (allocation-free rule: __device__ globals)
__device__ float g_out[Tdim * Bdim * Hdim];   // per-step top-layer outputs [T,B,H]
__device__ float g_h0[2][Bdim * Hdim];        // ping-pong hidden for layer 0

// ---------------------------------------------------------------------------
// RNN layer step:  hnew[i,j] = tanh( sum_k inp[i,k]*Wih[j,k]
//                                  + sum_k hprev[i,k]*Whh[j,k]
//                                  + bih[j] + bhh[j] )
// M=256, N=1024, K=1024(x2 operands). Tile BM=32, BN=64, BK=32, 128 threads,
// 4x4 micro-tile per thread. Grid (8,16) = 128 CTAs.
// ---------------------------------------------------------------------------
__global__ __launch_bounds__(128, 4)
void rnn_layer(const float* __restrict__ inp,
               const float* __restrict__ hprev,
               const float* __restrict__ Wih,
               const float* __restrict__ Whh,
               const float* __restrict__ bih,
               const float* __restrict__ bhh,
               float* __restrict__ hnew)
{
    __shared__ float As[32][33];
    __shared__ float Ws[64][33];

    const int bm = blockIdx.x * 32;
    const int bn = blockIdx.y * 64;
    const int tid = threadIdx.x;
    const int tx = tid & 15;        // 16 col-threads
    const int ty = tid >> 4;        // 8  row-threads
    const int r0 = ty * 4;
    const int c0 = tx * 4;

    const int lr = tid >> 3;        // 0..15 loader row
    const int lk = (tid & 7) * 4;   // 0..28 loader k (float4)

    float acc[4][4];
#pragma unroll
    for (int i = 0; i < 4; i++)
#pragma unroll
        for (int j = 0; j < 4; j++) acc[i][j] = 0.0f;

#pragma unroll 1
    for (int pass = 0; pass < 2; ++pass) {
        const float* A = pass ? hprev : inp;
        const float* W = pass ? Whh : Wih;

#pragma unroll 1
        for (int k0 = 0; k0 < Hdim; k0 += 32) {
            // Load A tile 32x32 (2 float4 per thread)
            {
                float4 a0 = *(const float4*)&A[(bm + lr) * Hdim + k0 + lk];
                float4 a1 = *(const float4*)&A[(bm + lr + 16) * Hdim + k0 + lk];
                As[lr][lk + 0] = a0.x; As[lr][lk + 1] = a0.y;
                As[lr][lk + 2] = a0.z; As[lr][lk + 3] = a0.w;
                As[lr + 16][lk + 0] = a1.x; As[lr + 16][lk + 1] = a1.y;
                As[lr + 16][lk + 2] = a1.z; As[lr + 16][lk + 3] = a1.w;
            }
            // Load W tile 64x32 (4 float4 per thread)
#pragma unroll
            for (int w = 0; w < 4; w++) {
                float4 b = *(const float4*)&W[(bn + lr + 16 * w) * Hdim + k0 + lk];
                Ws[lr + 16 * w][lk + 0] = b.x; Ws[lr + 16 * w][lk + 1] = b.y;
                Ws[lr + 16 * w][lk + 2] = b.z; Ws[lr + 16 * w][lk + 3] = b.w;
            }
            __syncthreads();

#pragma unroll
            for (int kk = 0; kk < 32; ++kk) {
                float a[4], w[4];
#pragma unroll
                for (int i = 0; i < 4; i++) a[i] = As[r0 + i][kk];
#pragma unroll
                for (int j = 0; j < 4; j++) w[j] = Ws[c0 + j][kk];
#pragma unroll
                for (int i = 0; i < 4; i++)
#pragma unroll
                    for (int j = 0; j < 4; j++)
                        acc[i][j] = fmaf(a[i], w[j], acc[i][j]);
            }
            __syncthreads();
        }
    }

#pragma unroll
    for (int j = 0; j < 4; j++) {
        const int col = bn + c0 + j;
        const float bias = bih[col] + bhh[col];
#pragma unroll
        for (int i = 0; i < 4; i++) {
            hnew[(bm + r0 + i) * Hdim + col] = tanhf(acc[i][j] + bias);
        }
    }
}

// ---------------------------------------------------------------------------
// Final projection, batched over all timesteps:
// out[r, o] = sum_k Out[r,k] * fcW[o,k] + fcb[o]
// M = T*B = 16384, N = 8192, K = 1024.
// Tile BM=64, BN=64, BK=32, 256 threads, 4x4 micro-tile.
// ---------------------------------------------------------------------------
__global__ __launch_bounds__(256, 2)
void fc_gemm(const float* __restrict__ A,      // [16384, 1024]
             const float* __restrict__ W,      // [8192, 1024]
             const float* __restrict__ bias,   // [8192]
             float* __restrict__ out)          // [16384, 8192]
{
    __shared__ float As[64][33];
    __shared__ float Ws[64][33];

    const int bm = blockIdx.x * 64;
    const int bn = blockIdx.y * 64;
    const int tid = threadIdx.x;
    const int tx = tid & 15;
    const int ty = tid >> 4;
    const int r0 = ty * 4;
    const int c0 = tx * 4;

    const int lr = tid >> 3;        // 0..31
    const int lk = (tid & 7) * 4;

    float acc[4][4];
#pragma unroll
    for (int i = 0; i < 4; i++)
#pragma unroll
        for (int j = 0; j < 4; j++) acc[i][j] = 0.0f;

#pragma unroll 1
    for (int k0 = 0; k0 < Hdim; k0 += 32) {
#pragma unroll
        for (int h = 0; h < 2; h++) {
            float4 a = *(const float4*)&A[(bm + lr + 32 * h) * Hdim + k0 + lk];
            As[lr + 32 * h][lk + 0] = a.x; As[lr + 32 * h][lk + 1] = a.y;
            As[lr + 32 * h][lk + 2] = a.z; As[lr + 32 * h][lk + 3] = a.w;
            float4 b = *(const float4*)&W[(bn + lr + 32 * h) * Hdim + k0 + lk];
            Ws[lr + 32 * h][lk + 0] = b.x; Ws[lr + 32 * h][lk + 1] = b.y;
            Ws[lr + 32 * h][lk + 2] = b.z; Ws[lr + 32 * h][lk + 3] = b.w;
        }
        __syncthreads();

#pragma unroll
        for (int kk = 0; kk < 32; ++kk) {
            float a[4], w[4];
#pragma unroll
            for (int i = 0; i < 4; i++) a[i] = As[r0 + i][kk];
#pragma unroll
            for (int j = 0; j < 4; j++) w[j] = Ws[c0 + j][kk];
#pragma unroll
            for (int i = 0; i < 4; i++)
#pragma unroll
                for (int j = 0; j < 4; j++)
                    acc[i][j] = fmaf(a[i], w[j], acc[i][j]);
        }
        __syncthreads();
    }

#pragma unroll
    for (int j = 0; j < 4; j++) {
        const int col = bn + c0 + j;
        const float bb = bias[col];
#pragma unroll
        for (int i = 0; i < 4; i++) {
            out[(size_t)(bm + r0 + i) * Odim + col] = acc[i][j] + bb;
        }
    }
}

extern "C" void kernel_launch(void* const* d_in, const int* in_sizes, int n_in,
                              void* d_out, int out_size)
{
    const float* x      = (const float*)d_in[0];  // [1,B,H]
    const float* hidden = (const float*)d_in[1];  // [L,B,H]
    // d_in[2] = embedded (only sets T; unused)
    const float* W_ih   = (const float*)d_in[3];  // [L,H,H]
    const float* W_hh   = (const float*)d_in[4];  // [L,H,H]
    const float* b_ih   = (const float*)d_in[5];  // [L,H]
    const float* b_hh   = (const float*)d_in[6];  // [L,H]
    const float* fc_W   = (const float*)d_in[7];  // [O,H]
    const float* fc_b   = (const float*)d_in[8];  // [O]
    float* out = (float*)d_out;

    float* outbuf = nullptr;
    float* h0buf  = nullptr;
    cudaGetSymbolAddress((void**)&outbuf, g_out);
    cudaGetSymbolAddress((void**)&h0buf, g_h0);

    const dim3 rnn_grid(Bdim / 32, Hdim / 64);   // (8,16)
    const dim3 rnn_blk(128);

    for (int t = 0; t < Tdim; ++t) {
        const float* inp0  = (t == 0) ? x : (outbuf + (size_t)(t - 1) * Bdim * Hdim);
        const float* h0prv = (t == 0) ? hidden
                                      : (h0buf + (size_t)((t - 1) & 1) * Bdim * Hdim);
        float* h0new = h0buf + (size_t)(t & 1) * Bdim * Hdim;

        // Layer 0
        rnn_layer<<<rnn_grid, rnn_blk>>>(inp0, h0prv,
                                         W_ih, W_hh, b_ih, b_hh, h0new);

        // Layer 1: h_prev is previous step's top output (== out[t-1]);
        // its new hidden IS the step output.
        const float* h1prv = (t == 0) ? (hidden + (size_t)Bdim * Hdim)
                                      : (outbuf + (size_t)(t - 1) * Bdim * Hdim);
        rnn_layer<<<rnn_grid, rnn_blk>>>(h0new, h1prv,
                                         W_ih + (size_t)Hdim * Hdim,
                                         W_hh + (size_t)Hdim * Hdim,
                                         b_ih + Hdim, b_hh + Hdim,
                                         outbuf + (size_t)t * Bdim * Hdim);
    }

    // One big batched projection over all T*B rows.
    const dim3 fc_grid((Tdim * Bdim) / 64, Odim / 64);  // (256,128)
    fc_gemm<<<fc_grid, 256>>>(outbuf, fc_W, fc_b, out);
}

// round 3
// speedup vs baseline: 2.2868x; 2.2868x over previous
#include <cuda_runtime.h>
#include <cuda_bf16.h>
#include <cstdint>
#include <math.h>

#define Hdim 1024
#define Bdim 256
#define Tdim 64
#define Odim 8192
#define MTOT (Tdim*Bdim)
#define PADK 40            // padded row stride (elements) for a BK=32 tile row

typedef __nv_bfloat16 bf16;

// ---------------- scratch (__device__ globals; allocation-free rule) -------
__device__ __align__(128) bf16 g_Wih_hi[2u*Hdim*Hdim];
__device__ __align__(128) bf16 g_Wih_lo[2u*Hdim*Hdim];
__device__ __align__(128) bf16 g_Whh_hi[2u*Hdim*Hdim];
__device__ __align__(128) bf16 g_Whh_lo[2u*Hdim*Hdim];
__device__ __align__(128) bf16 g_fcW_hi[(size_t)Odim*Hdim];
__device__ __align__(128) bf16 g_fcW_lo[(size_t)Odim*Hdim];
__device__ __align__(128) bf16 g_out_hi[(size_t)MTOT*Hdim];
__device__ __align__(128) bf16 g_out_lo[(size_t)MTOT*Hdim];
__device__ __align__(128) bf16 g_h0_hi[2u*Bdim*Hdim];
__device__ __align__(128) bf16 g_h0_lo[2u*Bdim*Hdim];
__device__ __align__(128) bf16 g_x_hi[Bdim*Hdim];
__device__ __align__(128) bf16 g_x_lo[Bdim*Hdim];
__device__ __align__(128) bf16 g_hid_hi[2u*Bdim*Hdim];
__device__ __align__(128) bf16 g_hid_lo[2u*Bdim*Hdim];

// ---------------- helpers --------------------------------------------------
__device__ __forceinline__ uint32_t smem_u32(const void* p) {
    uint32_t a;
    asm("{ .reg .u64 t; cvta.to.shared.u64 t, %1; cvt.u32.u64 %0, t; }"
        : "=r"(a) : "l"(p));
    return a;
}

__device__ __forceinline__ void ldsm4(uint32_t* r, uint32_t addr) {
    asm volatile("ldmatrix.sync.aligned.m8n8.x4.shared.b16 {%0,%1,%2,%3}, [%4];"
                 : "=r"(r[0]), "=r"(r[1]), "=r"(r[2]), "=r"(r[3]) : "r"(addr));
}

__device__ __forceinline__ void hmma(float* c, const uint32_t* a, const uint32_t* b) {
    asm volatile("mma.sync.aligned.m16n8k16.row.col.f32.bf16.bf16.f32 "
                 "{%0,%1,%2,%3}, {%4,%5,%6,%7}, {%8,%9}, {%0,%1,%2,%3};"
                 : "+f"(c[0]), "+f"(c[1]), "+f"(c[2]), "+f"(c[3])
                 : "r"(a[0]), "r"(a[1]), "r"(a[2]), "r"(a[3]),
                   "r"(b[0]), "r"(b[1]));
}

#define CP_ASYNC16(so, g) \
    asm volatile("cp.async.cg.shared.global [%0], [%1], 16;" :: "r"(so), "l"(g))
#define CP_COMMIT()  asm volatile("cp.async.commit_group;" ::: "memory")
#define CP_WAIT1()   asm volatile("cp.async.wait_group 1;" ::: "memory")
#define CP_WAIT0()   asm volatile("cp.async.wait_group 0;" ::: "memory")

// ---------------- fp32 -> (hi, lo) bf16 split ------------------------------
__global__ void split_kernel(const float* __restrict__ src,
                             bf16* __restrict__ hi, bf16* __restrict__ lo,
                             int n) {
    int i = blockIdx.x * blockDim.x + threadIdx.x;
    if (i < n) {
        float v = src[i];
        bf16 h = __float2bfloat16(v);
        hi[i] = h;
        lo[i] = __float2bfloat16(v - __bfloat162float(h));
    }
}

// ---------------- mma.sync bf16x3 GEMM -------------------------------------
// D[BM, BN] = sum over NPASS of A[pass] @ B[pass]^T   (K = 1024 per pass)
// A,B given as hi/lo bf16 pairs; combos (hi,hi)+(lo,hi)+(hi,lo) accumulated
// into the same fp32 frags. Epilogue: +bias0 (+bias1), optional tanh,
// write fp32 or (hi,lo)-bf16 split.
// 256 threads = 8 warps as 4(m) x 2(n).
template<int BM, int BN, int NPASS, int DO_TANH, int OUT_SPLIT>
__global__ void __launch_bounds__(256) gemm_mma(
    const bf16* __restrict__ Ah0, const bf16* __restrict__ Al0,
    const bf16* __restrict__ Bh0, const bf16* __restrict__ Bl0,
    const bf16* __restrict__ Ah1, const bf16* __restrict__ Al1,
    const bf16* __restrict__ Bh1, const bf16* __restrict__ Bl1,
    const float* __restrict__ bias0, const float* __restrict__ bias1,
    float* __restrict__ outf, bf16* __restrict__ oHi, bf16* __restrict__ oLo,
    int Nld)
{
    constexpr int MI = BM / 64;             // m16 tiles per warp
    constexpr int NI = BN / 16;             // n8 tiles per warp
    constexpr int NB = NI / 2;              // ldmatrix.x4 count for B (per hi/lo)
    constexpr int STAGE = (BM + BN) * 2 * PADK * 2;   // bytes per stage
    constexpr int CHK = Hdim / 32;          // K-blocks per pass
    constexpr int NIT = NPASS * CHK;
    constexpr int offAh = 0;
    constexpr int offAl = BM * PADK * 2;
    constexpr int offBh = 2 * BM * PADK * 2;
    constexpr int offBl = offBh + BN * PADK * 2;

    extern __shared__ char sm[];
    const uint32_t smb = smem_u32(sm);
    const int tid = threadIdx.x;
    const int wid = tid >> 5, lid = tid & 31;
    const int wm = wid & 3, wn = wid >> 2;
    const int bm = blockIdx.x * BM, bn = blockIdx.y * BN;

    const bf16* APtr[4] = {Ah0, Al0, Ah1, Al1};
    const bf16* BPtr[4] = {Bh0, Bl0, Bh1, Bl1};

    float acc[MI][NI][4];
#pragma unroll
    for (int mi = 0; mi < MI; mi++)
#pragma unroll
        for (int ni = 0; ni < NI; ni++)
#pragma unroll
            for (int q = 0; q < 4; q++) acc[mi][ni][q] = 0.0f;

    auto load_stage = [&](int it) {
        const int pidx = (NPASS == 2 && it >= CHK) ? 2 : 0;
        const int k0 = (it % CHK) * 32;
        const uint32_t sb = smb + (uint32_t)(it & 1) * STAGE;
        constexpr int CA = BM * 4, CB = BN * 4;
#pragma unroll
        for (int idx0 = 0; idx0 < 2 * CA + 2 * CB; idx0 += 256) {
            const int idx = idx0 + tid;
            const bf16* g;
            uint32_t so;
            if (idx < CA) {
                int row = idx >> 2, c = idx & 3;
                g = APtr[pidx] + (size_t)(bm + row) * Hdim + k0 + c * 8;
                so = sb + offAh + row * (PADK * 2) + c * 16;
            } else if (idx < 2 * CA) {
                int j = idx - CA; int row = j >> 2, c = j & 3;
                g = APtr[pidx + 1] + (size_t)(bm + row) * Hdim + k0 + c * 8;
                so = sb + offAl + row * (PADK * 2) + c * 16;
            } else if (idx < 2 * CA + CB) {
                int j = idx - 2 * CA; int row = j >> 2, c = j & 3;
                g = BPtr[pidx] + (size_t)(bn + row) * Hdim + k0 + c * 8;
                so = sb + offBh + row * (PADK * 2) + c * 16;
            } else {
                int j = idx - 2 * CA - CB; int row = j >> 2, c = j & 3;
                g = BPtr[pidx + 1] + (size_t)(bn + row) * Hdim + k0 + c * 8;
                so = sb + offBl + row * (PADK * 2) + c * 16;
            }
            CP_ASYNC16(so, g);
        }
    };

    load_stage(0);
    CP_COMMIT();

    for (int it = 0; it < NIT; ++it) {
        if (it + 1 < NIT) {
            load_stage(it + 1);
            CP_COMMIT();
            CP_WAIT1();
        } else {
            CP_WAIT0();
        }
        __syncthreads();

        const uint32_t sb = smb + (uint32_t)(it & 1) * STAGE;
#pragma unroll
        for (int kk = 0; kk < 32; kk += 16) {
            uint32_t ah[MI][4], al[MI][4];
#pragma unroll
            for (int mi = 0; mi < MI; mi++) {
                const int row = wm * (MI * 16) + mi * 16 + (lid & 15);
                const int col = kk + ((lid >> 4) << 3);
                const uint32_t off = row * (PADK * 2) + col * 2;
                ldsm4(ah[mi], sb + offAh + off);
                ldsm4(al[mi], sb + offAl + off);
            }
            uint32_t bh[NI][2], bl[NI][2];
#pragma unroll
            for (int nb = 0; nb < NB; nb++) {
                const int row = wn * (NI * 8) + nb * 16 + (lid & 7) + ((lid & 16) ? 8 : 0);
                const int col = kk + ((lid & 8) ? 8 : 0);
                const uint32_t off = row * (PADK * 2) + col * 2;
                uint32_t r[4];
                ldsm4(r, sb + offBh + off);
                bh[2 * nb][0] = r[0]; bh[2 * nb][1] = r[1];
                bh[2 * nb + 1][0] = r[2]; bh[2 * nb + 1][1] = r[3];
                ldsm4(r, sb + offBl + off);
                bl[2 * nb][0] = r[0]; bl[2 * nb][1] = r[1];
                bl[2 * nb + 1][0] = r[2]; bl[2 * nb + 1][1] = r[3];
            }
#pragma unroll
            for (int mi = 0; mi < MI; mi++)
#pragma unroll
                for (int ni = 0; ni < NI; ni++)
                    hmma(acc[mi][ni], ah[mi], bh[ni]);
#pragma unroll
            for (int mi = 0; mi < MI; mi++)
#pragma unroll
                for (int ni = 0; ni < NI; ni++)
                    hmma(acc[mi][ni], al[mi], bh[ni]);
#pragma unroll
            for (int mi = 0; mi < MI; mi++)
#pragma unroll
                for (int ni = 0; ni < NI; ni++)
                    hmma(acc[mi][ni], ah[mi], bl[ni]);
        }
        __syncthreads();
    }

    // ---------------- epilogue ----------------
#pragma unroll
    for (int mi = 0; mi < MI; mi++) {
#pragma unroll
        for (int ni = 0; ni < NI; ni++) {
            const int r = bm + wm * (MI * 16) + mi * 16 + (lid >> 2);
            const int col = bn + wn * (NI * 8) + ni * 8 + (lid & 3) * 2;
            float bv0 = bias0[col], bv1 = bias0[col + 1];
            if (bias1) { bv0 += bias1[col]; bv1 += bias1[col + 1]; }
#pragma unroll
            for (int h = 0; h < 2; h++) {
                const int rr = r + h * 8;
                float v0 = acc[mi][ni][2 * h + 0] + bv0;
                float v1 = acc[mi][ni][2 * h + 1] + bv1;
                if (DO_TANH) { v0 = tanhf(v0); v1 = tanhf(v1); }
                if (OUT_SPLIT) {
                    bf16 h0 = __float2bfloat16(v0);
                    bf16 h1 = __float2bfloat16(v1);
                    bf16 l0 = __float2bfloat16(v0 - __bfloat162float(h0));
                    bf16 l1 = __float2bfloat16(v1 - __bfloat162float(h1));
                    __nv_bfloat162 ph; ph.x = h0; ph.y = h1;
                    __nv_bfloat162 pl; pl.x = l0; pl.y = l1;
                    *(__nv_bfloat162*)(oHi + (size_t)rr * Nld + col) = ph;
                    *(__nv_bfloat162*)(oLo + (size_t)rr * Nld + col) = pl;
                } else {
                    float2 p; p.x = v0; p.y = v1;
                    *(float2*)(outf + (size_t)rr * Nld + col) = p;
                }
            }
        }
    }
}

// ---------------- host -----------------------------------------------------
static void split(const float* src, bf16* hi, bf16* lo, int n) {
    split_kernel<<<(n + 255) / 256, 256>>>(src, hi, lo, n);
}

extern "C" void kernel_launch(void* const* d_in, const int* in_sizes, int n_in,
                              void* d_out, int out_size)
{
    const float* x      = (const float*)d_in[0];
    const float* hidden = (const float*)d_in[1];
    const float* W_ih   = (const float*)d_in[3];
    const float* W_hh   = (const float*)d_in[4];
    const float* b_ih   = (const float*)d_in[5];
    const float* b_hh   = (const float*)d_in[6];
    const float* fc_W   = (const float*)d_in[7];
    const float* fc_b   = (const float*)d_in[8];
    float* out = (float*)d_out;

    bf16 *Wih_hi, *Wih_lo, *Whh_hi, *Whh_lo, *fcW_hi, *fcW_lo;
    bf16 *out_hi, *out_lo, *h0_hi, *h0_lo, *x_hi, *x_lo, *hid_hi, *hid_lo;
    cudaGetSymbolAddress((void**)&Wih_hi, g_Wih_hi);
    cudaGetSymbolAddress((void**)&Wih_lo, g_Wih_lo);
    cudaGetSymbolAddress((void**)&Whh_hi, g_Whh_hi);
    cudaGetSymbolAddress((void**)&Whh_lo, g_Whh_lo);
    cudaGetSymbolAddress((void**)&fcW_hi, g_fcW_hi);
    cudaGetSymbolAddress((void**)&fcW_lo, g_fcW_lo);
    cudaGetSymbolAddress((void**)&out_hi, g_out_hi);
    cudaGetSymbolAddress((void**)&out_lo, g_out_lo);
    cudaGetSymbolAddress((void**)&h0_hi, g_h0_hi);
    cudaGetSymbolAddress((void**)&h0_lo, g_h0_lo);
    cudaGetSymbolAddress((void**)&x_hi, g_x_hi);
    cudaGetSymbolAddress((void**)&x_lo, g_x_lo);
    cudaGetSymbolAddress((void**)&hid_hi, g_hid_hi);
    cudaGetSymbolAddress((void**)&hid_lo, g_hid_lo);

    split(W_ih, Wih_hi, Wih_lo, 2 * Hdim * Hdim);
    split(W_hh, Whh_hi, Whh_lo, 2 * Hdim * Hdim);
    split(fc_W, fcW_hi, fcW_lo, Odim * Hdim);
    split(x, x_hi, x_lo, Bdim * Hdim);
    split(hidden, hid_hi, hid_lo, 2 * Bdim * Hdim);

    const int BH = Bdim * Hdim;
    const size_t HH = (size_t)Hdim * Hdim;

    // RNN: BM=64, BN=32, 2 passes, tanh, split output.  grid (4,32) = 128 CTAs
    constexpr int SM_RNN = 2 * (64 + 32) * 2 * PADK * 2;    // 30720 B
    // fc: BM=128, BN=128, 1 pass, fp32 output.           grid (128,64)
    constexpr int SM_FC  = 2 * (128 + 128) * 2 * PADK * 2;  // 81920 B
    cudaFuncSetAttribute(gemm_mma<64, 32, 2, 1, 1>,
                         cudaFuncAttributeMaxDynamicSharedMemorySize, SM_RNN);
    cudaFuncSetAttribute(gemm_mma<128, 128, 1, 0, 0>,
                         cudaFuncAttributeMaxDynamicSharedMemorySize, SM_FC);

    const dim3 rnn_grid(Bdim / 64, Hdim / 32);   // (4, 32)
    for (int t = 0; t < Tdim; ++t) {
        const bf16* inp_h = (t == 0) ? x_hi : out_hi + (size_t)(t - 1) * BH;
        const bf16* inp_l = (t == 0) ? x_lo : out_lo + (size_t)(t - 1) * BH;
        const bf16* h0p_h = (t == 0) ? hid_hi : h0_hi + (size_t)((t - 1) & 1) * BH;
        const bf16* h0p_l = (t == 0) ? hid_lo : h0_lo + (size_t)((t - 1) & 1) * BH;
        bf16* h0n_h = h0_hi + (size_t)(t & 1) * BH;
        bf16* h0n_l = h0_lo + (size_t)(t & 1) * BH;

        gemm_mma<64, 32, 2, 1, 1><<<rnn_grid, 256, SM_RNN>>>(
            inp_h, inp_l, Wih_hi, Wih_lo,
            h0p_h, h0p_l, Whh_hi, Whh_lo,
            b_ih, b_hh,
            nullptr, h0n_h, h0n_l, Hdim);

        const bf16* h1p_h = (t == 0) ? hid_hi + BH : out_hi + (size_t)(t - 1) * BH;
        const bf16* h1p_l = (t == 0) ? hid_lo + BH : out_lo + (size_t)(t - 1) * BH;
        gemm_mma<64, 32, 2, 1, 1><<<rnn_grid, 256, SM_RNN>>>(
            h0n_h, h0n_l, Wih_hi + HH, Wih_lo + HH,
            h1p_h, h1p_l, Whh_hi + HH, Whh_lo + HH,
            b_ih + Hdim, b_hh + Hdim,
            nullptr, out_hi + (size_t)t * BH, out_lo + (size_t)t * BH, Hdim);
    }

    const dim3 fc_grid(MTOT / 128, Odim / 128);  // (128, 64)
    gemm_mma<128, 128, 1, 0, 0><<<fc_grid, 256, SM_FC>>>(
        out_hi, out_lo, fcW_hi, fcW_lo,
        nullptr, nullptr, nullptr, nullptr,
        fc_b, nullptr,
        out, nullptr, nullptr, Odim);
}

// round 4
// speedup vs baseline: 2.3059x; 1.0084x over previous
#include <cuda_runtime.h>
#include <cuda_bf16.h>
#include <cstdint>
#include <math.h>

#define Hdim 1024
#define Bdim 256
#define Tdim 64
#define Odim 8192
#define MTOT (Tdim*Bdim)
#define PADK 40
#define NCTA 128

typedef __nv_bfloat16 bf16;

// ---------------- scratch ---------------------------------------------------
__device__ __align__(128) bf16 g_Wih_hi[2u*Hdim*Hdim];
__device__ __align__(128) bf16 g_Wih_lo[2u*Hdim*Hdim];
__device__ __align__(128) bf16 g_Whh_hi[2u*Hdim*Hdim];
__device__ __align__(128) bf16 g_Whh_lo[2u*Hdim*Hdim];
__device__ __align__(128) bf16 g_fcW_hi[(size_t)Odim*Hdim];
__device__ __align__(128) bf16 g_fcW_lo[(size_t)Odim*Hdim];
__device__ __align__(128) bf16 g_out_hi[(size_t)MTOT*Hdim];
__device__ __align__(128) bf16 g_out_lo[(size_t)MTOT*Hdim];
__device__ __align__(128) bf16 g_h0_hi[2u*Bdim*Hdim];
__device__ __align__(128) bf16 g_h0_lo[2u*Bdim*Hdim];
__device__ __align__(128) bf16 g_x_hi[Bdim*Hdim];
__device__ __align__(128) bf16 g_x_lo[Bdim*Hdim];
__device__ __align__(128) bf16 g_hid_hi[2u*Bdim*Hdim];
__device__ __align__(128) bf16 g_hid_lo[2u*Bdim*Hdim];

// grid barrier state (statically zero; invariant restored every barrier)
__device__ unsigned g_bar_cnt;
__device__ volatile unsigned g_bar_gen;

// ---------------- helpers ---------------------------------------------------
__device__ __forceinline__ uint32_t smem_u32(const void* p) {
    uint32_t a;
    asm("{ .reg .u64 t; cvta.to.shared.u64 t, %1; cvt.u32.u64 %0, t; }"
        : "=r"(a) : "l"(p));
    return a;
}

__device__ __forceinline__ void ldsm4(uint32_t* r, uint32_t addr) {
    asm volatile("ldmatrix.sync.aligned.m8n8.x4.shared.b16 {%0,%1,%2,%3}, [%4];"
                 : "=r"(r[0]), "=r"(r[1]), "=r"(r[2]), "=r"(r[3]) : "r"(addr));
}

__device__ __forceinline__ void hmma(float* c, const uint32_t* a, const uint32_t* b) {
    asm volatile("mma.sync.aligned.m16n8k16.row.col.f32.bf16.bf16.f32 "
                 "{%0,%1,%2,%3}, {%4,%5,%6,%7}, {%8,%9}, {%0,%1,%2,%3};"
                 : "+f"(c[0]), "+f"(c[1]), "+f"(c[2]), "+f"(c[3])
                 : "r"(a[0]), "r"(a[1]), "r"(a[2]), "r"(a[3]),
                   "r"(b[0]), "r"(b[1]));
}

#define CP_ASYNC16(so, g) \
    asm volatile("cp.async.cg.shared.global [%0], [%1], 16;" :: "r"(so), "l"(g))
#define CP_COMMIT()  asm volatile("cp.async.commit_group;" ::: "memory")
#define CP_WAIT1()   asm volatile("cp.async.wait_group 1;" ::: "memory")
#define CP_WAIT0()   asm volatile("cp.async.wait_group 0;" ::: "memory")

__device__ __forceinline__ void grid_barrier() {
    __syncthreads();
    if (threadIdx.x == 0) {
        __threadfence();
        unsigned gen = g_bar_gen;
        if (atomicAdd(&g_bar_cnt, 1u) == NCTA - 1u) {
            atomicExch(&g_bar_cnt, 0u);
            __threadfence();
            g_bar_gen = gen + 1u;
        } else {
            while (g_bar_gen == gen) __nanosleep(64);
        }
    }
    __syncthreads();
}

// ---------------- vectorized fp32 -> (hi, lo) bf16 split (8 elems/thread) --
__global__ void split8_kernel(const float4* __restrict__ src,
                              uint4* __restrict__ hi, uint4* __restrict__ lo,
                              int n8) {
    int i = blockIdx.x * blockDim.x + threadIdx.x;
    if (i >= n8) return;
    float4 a = src[2 * i], b = src[2 * i + 1];
    float v[8] = {a.x, a.y, a.z, a.w, b.x, b.y, b.z, b.w};
    __nv_bfloat16 h[8], l[8];
#pragma unroll
    for (int k = 0; k < 8; k++) {
        h[k] = __float2bfloat16(v[k]);
        l[k] = __float2bfloat16(v[k] - __bfloat162float(h[k]));
    }
    uint4 ph, pl;
    ph.x = ((uint32_t)__bfloat16_as_ushort(h[1]) << 16) | __bfloat16_as_ushort(h[0]);
    ph.y = ((uint32_t)__bfloat16_as_ushort(h[3]) << 16) | __bfloat16_as_ushort(h[2]);
    ph.z = ((uint32_t)__bfloat16_as_ushort(h[5]) << 16) | __bfloat16_as_ushort(h[4]);
    ph.w = ((uint32_t)__bfloat16_as_ushort(h[7]) << 16) | __bfloat16_as_ushort(h[6]);
    pl.x = ((uint32_t)__bfloat16_as_ushort(l[1]) << 16) | __bfloat16_as_ushort(l[0]);
    pl.y = ((uint32_t)__bfloat16_as_ushort(l[3]) << 16) | __bfloat16_as_ushort(l[2]);
    pl.z = ((uint32_t)__bfloat16_as_ushort(l[5]) << 16) | __bfloat16_as_ushort(l[4]);
    pl.w = ((uint32_t)__bfloat16_as_ushort(l[7]) << 16) | __bfloat16_as_ushort(l[6]);
    hi[i] = ph;
    lo[i] = pl;
}

// ---------------- persistent RNN kernel -------------------------------------
// 128 CTAs, BM=64 x BN=32 tiles of the 256x1024 step-layer output.
// 128 phases (t, layer); each phase: D = A0@B0^T + A1@B1^T (K=1024 each),
// 3 bf16 hi/lo combos; epilogue tanh + hi/lo split write; grid barrier.
__global__ void __launch_bounds__(256) persistent_rnn(
    const bf16* __restrict__ xH,   const bf16* __restrict__ xL,
    const bf16* __restrict__ hidH, const bf16* __restrict__ hidL,
    const bf16* __restrict__ WihH, const bf16* __restrict__ WihL,
    const bf16* __restrict__ WhhH, const bf16* __restrict__ WhhL,
    const float* __restrict__ b_ih, const float* __restrict__ b_hh,
    bf16* __restrict__ outH, bf16* __restrict__ outL,
    bf16* __restrict__ h0H,  bf16* __restrict__ h0L)
{
    constexpr int BM = 64, BN = 32;
    constexpr int STAGE = (BM + BN) * 2 * PADK * 2;   // 15360 B
    constexpr int offAh = 0;
    constexpr int offAl = BM * PADK * 2;
    constexpr int offBh = 2 * BM * PADK * 2;
    constexpr int offBl = offBh + BN * PADK * 2;
    constexpr int BH = Bdim * Hdim;
    constexpr size_t HH = (size_t)Hdim * Hdim;

    extern __shared__ char sm[];
    const uint32_t smb = smem_u32(sm);
    const int tid = threadIdx.x;
    const int wid = tid >> 5, lid = tid & 31;
    const int wm = wid & 3, wn = wid >> 2;
    const int bm = (blockIdx.x & 3) * BM;
    const int bn = (blockIdx.x >> 2) * BN;

#pragma unroll 1
    for (int ph = 0; ph < 2 * Tdim; ++ph) {
        const int t = ph >> 1, layer = ph & 1;

        const bf16 *A0h, *A0l, *A1h, *A1l, *B0h, *B0l, *B1h, *B1l;
        const float *bi0, *bi1;
        bf16 *dH, *dL;
        if (layer == 0) {
            A0h = t ? outH + (size_t)(t - 1) * BH : xH;
            A0l = t ? outL + (size_t)(t - 1) * BH : xL;
            A1h = t ? h0H + (size_t)((t - 1) & 1) * BH : hidH;
            A1l = t ? h0L + (size_t)((t - 1) & 1) * BH : hidL;
            B0h = WihH; B0l = WihL; B1h = WhhH; B1l = WhhL;
            bi0 = b_ih; bi1 = b_hh;
            dH = h0H + (size_t)(t & 1) * BH;
            dL = h0L + (size_t)(t & 1) * BH;
        } else {
            A0h = h0H + (size_t)(t & 1) * BH;
            A0l = h0L + (size_t)(t & 1) * BH;
            A1h = t ? outH + (size_t)(t - 1) * BH : hidH + BH;
            A1l = t ? outL + (size_t)(t - 1) * BH : hidL + BH;
            B0h = WihH + HH; B0l = WihL + HH; B1h = WhhH + HH; B1l = WhhL + HH;
            bi0 = b_ih + Hdim; bi1 = b_hh + Hdim;
            dH = outH + (size_t)t * BH;
            dL = outL + (size_t)t * BH;
        }

        float acc[2][4];
#pragma unroll
        for (int ni = 0; ni < 2; ni++)
#pragma unroll
            for (int q = 0; q < 4; q++) acc[ni][q] = 0.0f;

        auto load_stage = [&](int it) {
            const bf16* pAh = (it >= 32) ? A1h : A0h;
            const bf16* pAl = (it >= 32) ? A1l : A0l;
            const bf16* pBh = (it >= 32) ? B1h : B0h;
            const bf16* pBl = (it >= 32) ? B1l : B0l;
            const int k0 = (it & 31) * 32;
            const uint32_t sb = smb + (uint32_t)(it & 1) * STAGE;
            // 768 x 16B transfers, 3 per thread
#pragma unroll
            for (int rep = 0; rep < 3; rep++) {
                const int idx = rep * 256 + tid;
                const bf16* g;
                uint32_t so;
                if (idx < 256) {                  // A hi: 64 rows x 4 chunks
                    int row = idx >> 2, c = idx & 3;
                    g = pAh + (size_t)(bm + row) * Hdim + k0 + c * 8;
                    so = sb + offAh + row * (PADK * 2) + c * 16;
                } else if (idx < 512) {           // A lo
                    int j = idx - 256; int row = j >> 2, c = j & 3;
                    g = pAl + (size_t)(bm + row) * Hdim + k0 + c * 8;
                    so = sb + offAl + row * (PADK * 2) + c * 16;
                } else if (idx < 640) {           // B hi: 32 rows x 4 chunks
                    int j = idx - 512; int row = j >> 2, c = j & 3;
                    g = pBh + (size_t)(bn + row) * Hdim + k0 + c * 8;
                    so = sb + offBh + row * (PADK * 2) + c * 16;
                } else {                          // B lo
                    int j = idx - 640; int row = j >> 2, c = j & 3;
                    g = pBl + (size_t)(bn + row) * Hdim + k0 + c * 8;
                    so = sb + offBl + row * (PADK * 2) + c * 16;
                }
                CP_ASYNC16(so, g);
            }
        };

        load_stage(0);
        CP_COMMIT();

#pragma unroll 1
        for (int it = 0; it < 64; ++it) {
            if (it + 1 < 64) {
                load_stage(it + 1);
                CP_COMMIT();
                CP_WAIT1();
            } else {
                CP_WAIT0();
            }
            __syncthreads();

            const uint32_t sb = smb + (uint32_t)(it & 1) * STAGE;
#pragma unroll
            for (int kk = 0; kk < 32; kk += 16) {
                uint32_t ah[4], al[4];
                {
                    const int row = wm * 16 + (lid & 15);
                    const int col = kk + ((lid >> 4) << 3);
                    const uint32_t off = row * (PADK * 2) + col * 2;
                    ldsm4(ah, sb + offAh + off);
                    ldsm4(al, sb + offAl + off);
                }
                uint32_t bh[2][2], bl[2][2];
                {
                    const int row = wn * 16 + (lid & 7) + ((lid & 16) ? 8 : 0);
                    const int col = kk + ((lid & 8) ? 8 : 0);
                    const uint32_t off = row * (PADK * 2) + col * 2;
                    uint32_t r[4];
                    ldsm4(r, sb + offBh + off);
                    bh[0][0] = r[0]; bh[0][1] = r[1]; bh[1][0] = r[2]; bh[1][1] = r[3];
                    ldsm4(r, sb + offBl + off);
                    bl[0][0] = r[0]; bl[0][1] = r[1]; bl[1][0] = r[2]; bl[1][1] = r[3];
                }
#pragma unroll
                for (int ni = 0; ni < 2; ni++) hmma(acc[ni], ah, bh[ni]);
#pragma unroll
                for (int ni = 0; ni < 2; ni++) hmma(acc[ni], al, bh[ni]);
#pragma unroll
                for (int ni = 0; ni < 2; ni++) hmma(acc[ni], ah, bl[ni]);
            }
            __syncthreads();
        }

        // epilogue: bias + tanh + split
#pragma unroll
        for (int ni = 0; ni < 2; ni++) {
            const int r = bm + wm * 16 + (lid >> 2);
            const int col = bn + wn * 16 + ni * 8 + (lid & 3) * 2;
            const float bv0 = bi0[col] + bi1[col];
            const float bv1 = bi0[col + 1] + bi1[col + 1];
#pragma unroll
            for (int hh2 = 0; hh2 < 2; hh2++) {
                const int rr = r + hh2 * 8;
                float v0 = tanhf(acc[ni][2 * hh2 + 0] + bv0);
                float v1 = tanhf(acc[ni][2 * hh2 + 1] + bv1);
                bf16 h0v = __float2bfloat16(v0);
                bf16 h1v = __float2bfloat16(v1);
                bf16 l0v = __float2bfloat16(v0 - __bfloat162float(h0v));
                bf16 l1v = __float2bfloat16(v1 - __bfloat162float(h1v));
                __nv_bfloat162 phv; phv.x = h0v; phv.y = h1v;
                __nv_bfloat162 plv; plv.x = l0v; plv.y = l1v;
                *(__nv_bfloat162*)(dH + (size_t)rr * Hdim + col) = phv;
                *(__nv_bfloat162*)(dL + (size_t)rr * Hdim + col) = plv;
            }
        }

        grid_barrier();
    }
}

// ---------------- fc GEMM (unchanged from round 3, fc config only) ----------
__global__ void __launch_bounds__(256) fc_gemm(
    const bf16* __restrict__ Ah, const bf16* __restrict__ Al,
    const bf16* __restrict__ Bh, const bf16* __restrict__ Bl,
    const float* __restrict__ bias, float* __restrict__ outf)
{
    constexpr int BM = 128, BN = 128;
    constexpr int MI = 2, NI = 8, NB = 4;
    constexpr int STAGE = (BM + BN) * 2 * PADK * 2;
    constexpr int offAh = 0;
    constexpr int offAl = BM * PADK * 2;
    constexpr int offBh = 2 * BM * PADK * 2;
    constexpr int offBl = offBh + BN * PADK * 2;

    extern __shared__ char sm[];
    const uint32_t smb = smem_u32(sm);
    const int tid = threadIdx.x;
    const int wid = tid >> 5, lid = tid & 31;
    const int wm = wid & 3, wn = wid >> 2;
    const int bm = blockIdx.x * BM, bn = blockIdx.y * BN;

    float acc[MI][NI][4];
#pragma unroll
    for (int mi = 0; mi < MI; mi++)
#pragma unroll
        for (int ni = 0; ni < NI; ni++)
#pragma unroll
            for (int q = 0; q < 4; q++) acc[mi][ni][q] = 0.0f;

    auto load_stage = [&](int it) {
        const int k0 = it * 32;
        const uint32_t sb = smb + (uint32_t)(it & 1) * STAGE;
        constexpr int CA = BM * 4, CB = BN * 4;
#pragma unroll
        for (int idx0 = 0; idx0 < 2 * CA + 2 * CB; idx0 += 256) {
            const int idx = idx0 + tid;
            const bf16* g;
            uint32_t so;
            if (idx < CA) {
                int row = idx >> 2, c = idx & 3;
                g = Ah + (size_t)(bm + row) * Hdim + k0 + c * 8;
                so = sb + offAh + row * (PADK * 2) + c * 16;
            } else if (idx < 2 * CA) {
                int j = idx - CA; int row = j >> 2, c = j & 3;
                g = Al + (size_t)(bm + row) * Hdim + k0 + c * 8;
                so = sb + offAl + row * (PADK * 2) + c * 16;
            } else if (idx < 2 * CA + CB) {
                int j = idx - 2 * CA; int row = j >> 2, c = j & 3;
                g = Bh + (size_t)(bn + row) * Hdim + k0 + c * 8;
                so = sb + offBh + row * (PADK * 2) + c * 16;
            } else {
                int j = idx - 2 * CA - CB; int row = j >> 2, c = j & 3;
                g = Bl + (size_t)(bn + row) * Hdim + k0 + c * 8;
                so = sb + offBl + row * (PADK * 2) + c * 16;
            }
            CP_ASYNC16(so, g);
        }
    };

    load_stage(0);
    CP_COMMIT();

#pragma unroll 1
    for (int it = 0; it < 32; ++it) {
        if (it + 1 < 32) {
            load_stage(it + 1);
            CP_COMMIT();
            CP_WAIT1();
        } else {
            CP_WAIT0();
        }
        __syncthreads();

        const uint32_t sb = smb + (uint32_t)(it & 1) * STAGE;
#pragma unroll
        for (int kk = 0; kk < 32; kk += 16) {
            uint32_t ah[MI][4], al[MI][4];
#pragma unroll
            for (int mi = 0; mi < MI; mi++) {
                const int row = wm * (MI * 16) + mi * 16 + (lid & 15);
                const int col = kk + ((lid >> 4) << 3);
                const uint32_t off = row * (PADK * 2) + col * 2;
                ldsm4(ah[mi], sb + offAh + off);
                ldsm4(al[mi], sb + offAl + off);
            }
            uint32_t bh[NI][2], bl[NI][2];
#pragma unroll
            for (int nb = 0; nb < NB; nb++) {
                const int row = wn * (NI * 8) + nb * 16 + (lid & 7) + ((lid & 16) ? 8 : 0);
                const int col = kk + ((lid & 8) ? 8 : 0);
                const uint32_t off = row * (PADK * 2) + col * 2;
                uint32_t r[4];
                ldsm4(r, sb + offBh + off);
                bh[2 * nb][0] = r[0]; bh[2 * nb][1] = r[1];
                bh[2 * nb + 1][0] = r[2]; bh[2 * nb + 1][1] = r[3];
                ldsm4(r, sb + offBl + off);
                bl[2 * nb][0] = r[0]; bl[2 * nb][1] = r[1];
                bl[2 * nb + 1][0] = r[2]; bl[2 * nb + 1][1] = r[3];
            }
#pragma unroll
            for (int mi = 0; mi < MI; mi++)
#pragma unroll
                for (int ni = 0; ni < NI; ni++)
                    hmma(acc[mi][ni], ah[mi], bh[ni]);
#pragma unroll
            for (int mi = 0; mi < MI; mi++)
#pragma unroll
                for (int ni = 0; ni < NI; ni++)
                    hmma(acc[mi][ni], al[mi], bh[ni]);
#pragma unroll
            for (int mi = 0; mi < MI; mi++)
#pragma unroll
                for (int ni = 0; ni < NI; ni++)
                    hmma(acc[mi][ni], ah[mi], bl[ni]);
        }
        __syncthreads();
    }

#pragma unroll
    for (int mi = 0; mi < MI; mi++) {
#pragma unroll
        for (int ni = 0; ni < NI; ni++) {
            const int r = bm + wm * (MI * 16) + mi * 16 + (lid >> 2);
            const int col = bn + wn * (NI * 8) + ni * 8 + (lid & 3) * 2;
            const float bv0 = bias[col], bv1 = bias[col + 1];
#pragma unroll
            for (int h = 0; h < 2; h++) {
                const int rr = r + h * 8;
                float2 p;
                p.x = acc[mi][ni][2 * h + 0] + bv0;
                p.y = acc[mi][ni][2 * h + 1] + bv1;
                *(float2*)(outf + (size_t)rr * Odim + col) = p;
            }
        }
    }
}

// ---------------- host -------------------------------------------------------
static void split(const float* src, bf16* hi, bf16* lo, int n) {
    int n8 = n / 8;
    split8_kernel<<<(n8 + 255) / 256, 256>>>(
        (const float4*)src, (uint4*)hi, (uint4*)lo, n8);
}

extern "C" void kernel_launch(void* const* d_in, const int* in_sizes, int n_in,
                              void* d_out, int out_size)
{
    const float* x      = (const float*)d_in[0];
    const float* hidden = (const float*)d_in[1];
    const float* W_ih   = (const float*)d_in[3];
    const float* W_hh   = (const float*)d_in[4];
    const float* b_ih   = (const float*)d_in[5];
    const float* b_hh   = (const float*)d_in[6];
    const float* fc_W   = (const float*)d_in[7];
    const float* fc_b   = (const float*)d_in[8];
    float* out = (float*)d_out;

    bf16 *Wih_hi, *Wih_lo, *Whh_hi, *Whh_lo, *fcW_hi, *fcW_lo;
    bf16 *out_hi, *out_lo, *h0_hi, *h0_lo, *x_hi, *x_lo, *hid_hi, *hid_lo;
    cudaGetSymbolAddress((void**)&Wih_hi, g_Wih_hi);
    cudaGetSymbolAddress((void**)&Wih_lo, g_Wih_lo);
    cudaGetSymbolAddress((void**)&Whh_hi, g_Whh_hi);
    cudaGetSymbolAddress((void**)&Whh_lo, g_Whh_lo);
    cudaGetSymbolAddress((void**)&fcW_hi, g_fcW_hi);
    cudaGetSymbolAddress((void**)&fcW_lo, g_fcW_lo);
    cudaGetSymbolAddress((void**)&out_hi, g_out_hi);
    cudaGetSymbolAddress((void**)&out_lo, g_out_lo);
    cudaGetSymbolAddress((void**)&h0_hi, g_h0_hi);
    cudaGetSymbolAddress((void**)&h0_lo, g_h0_lo);
    cudaGetSymbolAddress((void**)&x_hi, g_x_hi);
    cudaGetSymbolAddress((void**)&x_lo, g_x_lo);
    cudaGetSymbolAddress((void**)&hid_hi, g_hid_hi);
    cudaGetSymbolAddress((void**)&hid_lo, g_hid_lo);

    split(W_ih, Wih_hi, Wih_lo, 2 * Hdim * Hdim);
    split(W_hh, Whh_hi, Whh_lo, 2 * Hdim * Hdim);
    split(fc_W, fcW_hi, fcW_lo, Odim * Hdim);
    split(x, x_hi, x_lo, Bdim * Hdim);
    split(hidden, hid_hi, hid_lo, 2 * Bdim * Hdim);

    constexpr int SM_RNN = 2 * (64 + 32) * 2 * PADK * 2;     // 30720 B
    constexpr int SM_FC  = 2 * (128 + 128) * 2 * PADK * 2;   // 81920 B
    cudaFuncSetAttribute(persistent_rnn,
                         cudaFuncAttributeMaxDynamicSharedMemorySize, SM_RNN);
    cudaFuncSetAttribute(fc_gemm,
                         cudaFuncAttributeMaxDynamicSharedMemorySize, SM_FC);

    persistent_rnn<<<NCTA, 256, SM_RNN>>>(
        x_hi, x_lo, hid_hi, hid_lo,
        Wih_hi, Wih_lo, Whh_hi, Whh_lo,
        b_ih, b_hh,
        out_hi, out_lo, h0_hi, h0_lo);

    const dim3 fc_grid(MTOT / 128, Odim / 128);  // (128, 64)
    fc_gemm<<<fc_grid, 256, SM_FC>>>(
        out_hi, out_lo, fcW_hi, fcW_lo, fc_b, out);
}

// round 5
// speedup vs baseline: 2.7994x; 1.2140x over previous
#include <cuda_runtime.h>
#include <cuda_bf16.h>
#include <cstdint>
#include <math.h>

#define Hdim 1024
#define Bdim 256
#define Tdim 64
#define Odim 8192
#define MTOT (Tdim*Bdim)
#define NCTA 128
#define RSTR 144           // row stride bytes for a BK=64 tile row (72 bf16)

typedef __nv_bfloat16 bf16;

// ---------------- scratch ---------------------------------------------------
__device__ __align__(128) bf16 g_Wih_hi[2u*Hdim*Hdim];
__device__ __align__(128) bf16 g_Wih_lo[2u*Hdim*Hdim];
__device__ __align__(128) bf16 g_Whh_hi[2u*Hdim*Hdim];
__device__ __align__(128) bf16 g_Whh_lo[2u*Hdim*Hdim];
__device__ __align__(128) bf16 g_fcW_hi[(size_t)Odim*Hdim];
__device__ __align__(128) bf16 g_fcW_lo[(size_t)Odim*Hdim];
__device__ __align__(128) bf16 g_out_hi[(size_t)MTOT*Hdim];
__device__ __align__(128) bf16 g_out_lo[(size_t)MTOT*Hdim];
__device__ __align__(128) bf16 g_h0_hi[2u*Bdim*Hdim];
__device__ __align__(128) bf16 g_h0_lo[2u*Bdim*Hdim];
__device__ __align__(128) bf16 g_x_hi[Bdim*Hdim];
__device__ __align__(128) bf16 g_x_lo[Bdim*Hdim];
__device__ __align__(128) bf16 g_hid_hi[2u*Bdim*Hdim];
__device__ __align__(128) bf16 g_hid_lo[2u*Bdim*Hdim];

__device__ unsigned g_bar_cnt;
__device__ volatile unsigned g_bar_gen;

// ---------------- helpers ---------------------------------------------------
__device__ __forceinline__ uint32_t smem_u32(const void* p) {
    uint32_t a;
    asm("{ .reg .u64 t; cvta.to.shared.u64 t, %1; cvt.u32.u64 %0, t; }"
        : "=r"(a) : "l"(p));
    return a;
}

__device__ __forceinline__ void ldsm4(uint32_t* r, uint32_t addr) {
    asm volatile("ldmatrix.sync.aligned.m8n8.x4.shared.b16 {%0,%1,%2,%3}, [%4];"
                 : "=r"(r[0]), "=r"(r[1]), "=r"(r[2]), "=r"(r[3]) : "r"(addr));
}

__device__ __forceinline__ void hmma(float* c, const uint32_t* a, const uint32_t* b) {
    asm volatile("mma.sync.aligned.m16n8k16.row.col.f32.bf16.bf16.f32 "
                 "{%0,%1,%2,%3}, {%4,%5,%6,%7}, {%8,%9}, {%0,%1,%2,%3};"
                 : "+f"(c[0]), "+f"(c[1]), "+f"(c[2]), "+f"(c[3])
                 : "r"(a[0]), "r"(a[1]), "r"(a[2]), "r"(a[3]),
                   "r"(b[0]), "r"(b[1]));
}

#define CP_ASYNC16(so, g) \
    asm volatile("cp.async.cg.shared.global [%0], [%1], 16;" :: "r"(so), "l"(g))
#define CP_COMMIT()  asm volatile("cp.async.commit_group;" ::: "memory")
#define CP_WAIT2()   asm volatile("cp.async.wait_group 2;" ::: "memory")
#define CP_WAIT1()   asm volatile("cp.async.wait_group 1;" ::: "memory")
#define CP_WAIT0()   asm volatile("cp.async.wait_group 0;" ::: "memory")

__device__ __forceinline__ void grid_barrier() {
    __syncthreads();
    if (threadIdx.x == 0) {
        __threadfence();
        unsigned gen = g_bar_gen;
        if (atomicAdd(&g_bar_cnt, 1u) == NCTA - 1u) {
            atomicExch(&g_bar_cnt, 0u);
            __threadfence();
            g_bar_gen = gen + 1u;
        } else {
            while (g_bar_gen == gen) __nanosleep(64);
        }
    }
    __syncthreads();
}

// ---------------- vectorized split ------------------------------------------
__global__ void split8_kernel(const float4* __restrict__ src,
                              uint4* __restrict__ hi, uint4* __restrict__ lo,
                              int n8) {
    int i = blockIdx.x * blockDim.x + threadIdx.x;
    if (i >= n8) return;
    float4 a = src[2 * i], b = src[2 * i + 1];
    float v[8] = {a.x, a.y, a.z, a.w, b.x, b.y, b.z, b.w};
    __nv_bfloat16 h[8], l[8];
#pragma unroll
    for (int k = 0; k < 8; k++) {
        h[k] = __float2bfloat16(v[k]);
        l[k] = __float2bfloat16(v[k] - __bfloat162float(h[k]));
    }
    uint4 ph, pl;
    ph.x = ((uint32_t)__bfloat16_as_ushort(h[1]) << 16) | __bfloat16_as_ushort(h[0]);
    ph.y = ((uint32_t)__bfloat16_as_ushort(h[3]) << 16) | __bfloat16_as_ushort(h[2]);
    ph.z = ((uint32_t)__bfloat16_as_ushort(h[5]) << 16) | __bfloat16_as_ushort(h[4]);
    ph.w = ((uint32_t)__bfloat16_as_ushort(h[7]) << 16) | __bfloat16_as_ushort(h[6]);
    pl.x = ((uint32_t)__bfloat16_as_ushort(l[1]) << 16) | __bfloat16_as_ushort(l[0]);
    pl.y = ((uint32_t)__bfloat16_as_ushort(l[3]) << 16) | __bfloat16_as_ushort(l[2]);
    pl.z = ((uint32_t)__bfloat16_as_ushort(l[5]) << 16) | __bfloat16_as_ushort(l[4]);
    pl.w = ((uint32_t)__bfloat16_as_ushort(l[7]) << 16) | __bfloat16_as_ushort(l[6]);
    hi[i] = ph;
    lo[i] = pl;
}

// ---------------- persistent RNN --------------------------------------------
// 128 CTAs; BM=64 x BN=32 tiles; BK=64; 4-stage cp.async pipeline.
__global__ void __launch_bounds__(256) persistent_rnn(
    const bf16* __restrict__ xH,   const bf16* __restrict__ xL,
    const bf16* __restrict__ hidH, const bf16* __restrict__ hidL,
    const bf16* __restrict__ WihH, const bf16* __restrict__ WihL,
    const bf16* __restrict__ WhhH, const bf16* __restrict__ WhhL,
    const float* __restrict__ b_ih, const float* __restrict__ b_hh,
    bf16* __restrict__ outH, bf16* __restrict__ outL,
    bf16* __restrict__ h0H,  bf16* __restrict__ h0L)
{
    constexpr int STAGE = 192 * RSTR;        // 27648 B (64+64+32+32 row slots)
    constexpr int offAl = 64 * RSTR;
    constexpr int offBh = 128 * RSTR;
    constexpr int offBl = 160 * RSTR;
    constexpr int BH = Bdim * Hdim;
    constexpr size_t HH = (size_t)Hdim * Hdim;

    extern __shared__ char sm[];
    const uint32_t smb = smem_u32(sm);
    const int tid = threadIdx.x;
    const int wid = tid >> 5, lid = tid & 31;
    const int wm = wid & 3, wn = wid >> 2;
    const int bm = (blockIdx.x & 3) * 64;
    const int bn = (blockIdx.x >> 2) * 32;

#pragma unroll 1
    for (int ph = 0; ph < 2 * Tdim; ++ph) {
        const int t = ph >> 1, layer = ph & 1;

        const bf16 *A0h, *A0l, *A1h, *A1l, *B0h, *B0l, *B1h, *B1l;
        const float *bi0, *bi1;
        bf16 *dH, *dL;
        if (layer == 0) {
            A0h = t ? outH + (size_t)(t - 1) * BH : xH;
            A0l = t ? outL + (size_t)(t - 1) * BH : xL;
            A1h = t ? h0H + (size_t)((t - 1) & 1) * BH : hidH;
            A1l = t ? h0L + (size_t)((t - 1) & 1) * BH : hidL;
            B0h = WihH; B0l = WihL; B1h = WhhH; B1l = WhhL;
            bi0 = b_ih; bi1 = b_hh;
            dH = h0H + (size_t)(t & 1) * BH;
            dL = h0L + (size_t)(t & 1) * BH;
        } else {
            A0h = h0H + (size_t)(t & 1) * BH;
            A0l = h0L + (size_t)(t & 1) * BH;
            A1h = t ? outH + (size_t)(t - 1) * BH : hidH + BH;
            A1l = t ? outL + (size_t)(t - 1) * BH : hidL + BH;
            B0h = WihH + HH; B0l = WihL + HH; B1h = WhhH + HH; B1l = WhhL + HH;
            bi0 = b_ih + Hdim; bi1 = b_hh + Hdim;
            dH = outH + (size_t)t * BH;
            dL = outL + (size_t)t * BH;
        }

        float acc[2][4];
#pragma unroll
        for (int ni = 0; ni < 2; ni++)
#pragma unroll
            for (int q = 0; q < 4; q++) acc[ni][q] = 0.0f;

        auto load_stage = [&](int it) {
            const bf16* pAh = (it >= 16) ? A1h : A0h;
            const bf16* pAl = (it >= 16) ? A1l : A0l;
            const bf16* pBh = (it >= 16) ? B1h : B0h;
            const bf16* pBl = (it >= 16) ? B1l : B0l;
            const int k0 = (it & 15) * 64;
            const uint32_t sb = smb + (uint32_t)(it & 3) * STAGE;
            // 192 row slots x 8 chunks = 1536 x 16B; 6 per thread
#pragma unroll
            for (int rep = 0; rep < 6; rep++) {
                const int idx = rep * 256 + tid;
                const int slot = idx >> 3, c = idx & 7;
                const uint32_t so = sb + slot * RSTR + c * 16;
                const bf16* g;
                if (slot < 64)       g = pAh + (size_t)(bm + slot) * Hdim + k0 + c * 8;
                else if (slot < 128) g = pAl + (size_t)(bm + slot - 64) * Hdim + k0 + c * 8;
                else if (slot < 160) g = pBh + (size_t)(bn + slot - 128) * Hdim + k0 + c * 8;
                else                 g = pBl + (size_t)(bn + slot - 160) * Hdim + k0 + c * 8;
                CP_ASYNC16(so, g);
            }
        };

        load_stage(0); CP_COMMIT();
        load_stage(1); CP_COMMIT();
        load_stage(2); CP_COMMIT();

#pragma unroll 1
        for (int it = 0; it < 32; ++it) {
            CP_WAIT2();
            __syncthreads();
            if (it + 3 < 32) { load_stage(it + 3); CP_COMMIT(); }
            else { CP_COMMIT(); }   // keep group count consistent

            const uint32_t sb = smb + (uint32_t)(it & 3) * STAGE;
#pragma unroll
            for (int kk = 0; kk < 4; kk++) {
                uint32_t ah[4], al[4];
                {
                    const int row = wm * 16 + (lid & 15);
                    const int col = kk * 16 + ((lid >> 4) << 3);
                    const uint32_t off = row * RSTR + col * 2;
                    ldsm4(ah, sb + off);
                    ldsm4(al, sb + offAl + off);
                }
                uint32_t bh[2][2], bl[2][2];
                {
                    const int row = wn * 16 + (lid & 7) + ((lid & 16) ? 8 : 0);
                    const int col = kk * 16 + ((lid & 8) ? 8 : 0);
                    const uint32_t off = row * RSTR + col * 2;
                    uint32_t r[4];
                    ldsm4(r, sb + offBh + off);
                    bh[0][0] = r[0]; bh[0][1] = r[1]; bh[1][0] = r[2]; bh[1][1] = r[3];
                    ldsm4(r, sb + offBl + off);
                    bl[0][0] = r[0]; bl[0][1] = r[1]; bl[1][0] = r[2]; bl[1][1] = r[3];
                }
#pragma unroll
                for (int ni = 0; ni < 2; ni++) hmma(acc[ni], ah, bh[ni]);
#pragma unroll
                for (int ni = 0; ni < 2; ni++) hmma(acc[ni], al, bh[ni]);
#pragma unroll
                for (int ni = 0; ni < 2; ni++) hmma(acc[ni], ah, bl[ni]);
            }
        }
        CP_WAIT0();

        // epilogue: bias + tanh + hi/lo split write
#pragma unroll
        for (int ni = 0; ni < 2; ni++) {
            const int r = bm + wm * 16 + (lid >> 2);
            const int col = bn + wn * 16 + ni * 8 + (lid & 3) * 2;
            const float bv0 = bi0[col] + bi1[col];
            const float bv1 = bi0[col + 1] + bi1[col + 1];
#pragma unroll
            for (int hh2 = 0; hh2 < 2; hh2++) {
                const int rr = r + hh2 * 8;
                float v0 = tanhf(acc[ni][2 * hh2 + 0] + bv0);
                float v1 = tanhf(acc[ni][2 * hh2 + 1] + bv1);
                bf16 h0v = __float2bfloat16(v0);
                bf16 h1v = __float2bfloat16(v1);
                bf16 l0v = __float2bfloat16(v0 - __bfloat162float(h0v));
                bf16 l1v = __float2bfloat16(v1 - __bfloat162float(h1v));
                __nv_bfloat162 phv; phv.x = h0v; phv.y = h1v;
                __nv_bfloat162 plv; plv.x = l0v; plv.y = l1v;
                *(__nv_bfloat162*)(dH + (size_t)rr * Hdim + col) = phv;
                *(__nv_bfloat162*)(dL + (size_t)rr * Hdim + col) = plv;
            }
        }

        grid_barrier();
    }
}

// ---------------- fc GEMM: BM=128 BN=128 BK=64, 3-stage --------------------
__global__ void __launch_bounds__(256) fc_gemm(
    const bf16* __restrict__ Ah, const bf16* __restrict__ Al,
    const bf16* __restrict__ Bh, const bf16* __restrict__ Bl,
    const float* __restrict__ bias, float* __restrict__ outf)
{
    constexpr int STAGE = 512 * RSTR;        // 73728 B
    constexpr int offAl = 128 * RSTR;
    constexpr int offBh = 256 * RSTR;
    constexpr int offBl = 384 * RSTR;

    extern __shared__ char sm[];
    const uint32_t smb = smem_u32(sm);
    const int tid = threadIdx.x;
    const int wid = tid >> 5, lid = tid & 31;
    const int wm = wid & 3, wn = wid >> 2;
    const int bm = blockIdx.x * 128, bn = blockIdx.y * 128;

    float acc[2][8][4];
#pragma unroll
    for (int mi = 0; mi < 2; mi++)
#pragma unroll
        for (int ni = 0; ni < 8; ni++)
#pragma unroll
            for (int q = 0; q < 4; q++) acc[mi][ni][q] = 0.0f;

    auto load_stage = [&](int it) {
        const int k0 = it * 64;
        const uint32_t sb = smb + (uint32_t)(it % 3) * STAGE;
        // 512 slots x 8 chunks = 4096 x 16B; 16 per thread
#pragma unroll
        for (int rep = 0; rep < 16; rep++) {
            const int idx = rep * 256 + tid;
            const int slot = idx >> 3, c = idx & 7;
            const uint32_t so = sb + slot * RSTR + c * 16;
            const bf16* g;
            if (slot < 128)      g = Ah + (size_t)(bm + slot) * Hdim + k0 + c * 8;
            else if (slot < 256) g = Al + (size_t)(bm + slot - 128) * Hdim + k0 + c * 8;
            else if (slot < 384) g = Bh + (size_t)(bn + slot - 256) * Hdim + k0 + c * 8;
            else                 g = Bl + (size_t)(bn + slot - 384) * Hdim + k0 + c * 8;
            CP_ASYNC16(so, g);
        }
    };

    load_stage(0); CP_COMMIT();
    load_stage(1); CP_COMMIT();

#pragma unroll 1
    for (int it = 0; it < 16; ++it) {
        CP_WAIT1();
        __syncthreads();
        if (it + 2 < 16) { load_stage(it + 2); CP_COMMIT(); }
        else { CP_COMMIT(); }

        const uint32_t sb = smb + (uint32_t)(it % 3) * STAGE;
#pragma unroll
        for (int kk = 0; kk < 4; kk++) {
            uint32_t ah[2][4], al[2][4];
#pragma unroll
            for (int mi = 0; mi < 2; mi++) {
                const int row = wm * 32 + mi * 16 + (lid & 15);
                const int col = kk * 16 + ((lid >> 4) << 3);
                const uint32_t off = row * RSTR + col * 2;
                ldsm4(ah[mi], sb + off);
                ldsm4(al[mi], sb + offAl + off);
            }
            uint32_t bh[8][2], bl[8][2];
#pragma unroll
            for (int nb = 0; nb < 4; nb++) {
                const int row = wn * 64 + nb * 16 + (lid & 7) + ((lid & 16) ? 8 : 0);
                const int col = kk * 16 + ((lid & 8) ? 8 : 0);
                const uint32_t off = row * RSTR + col * 2;
                uint32_t r[4];
                ldsm4(r, sb + offBh + off);
                bh[2 * nb][0] = r[0]; bh[2 * nb][1] = r[1];
                bh[2 * nb + 1][0] = r[2]; bh[2 * nb + 1][1] = r[3];
                ldsm4(r, sb + offBl + off);
                bl[2 * nb][0] = r[0]; bl[2 * nb][1] = r[1];
                bl[2 * nb + 1][0] = r[2]; bl[2 * nb + 1][1] = r[3];
            }
#pragma unroll
            for (int mi = 0; mi < 2; mi++)
#pragma unroll
                for (int ni = 0; ni < 8; ni++)
                    hmma(acc[mi][ni], ah[mi], bh[ni]);
#pragma unroll
            for (int mi = 0; mi < 2; mi++)
#pragma unroll
                for (int ni = 0; ni < 8; ni++)
                    hmma(acc[mi][ni], al[mi], bh[ni]);
#pragma unroll
            for (int mi = 0; mi < 2; mi++)
#pragma unroll
                for (int ni = 0; ni < 8; ni++)
                    hmma(acc[mi][ni], ah[mi], bl[ni]);
        }
    }
    CP_WAIT0();

#pragma unroll
    for (int mi = 0; mi < 2; mi++) {
#pragma unroll
        for (int ni = 0; ni < 8; ni++) {
            const int r = bm + wm * 32 + mi * 16 + (lid >> 2);
            const int col = bn + wn * 64 + ni * 8 + (lid & 3) * 2;
            const float bv0 = bias[col], bv1 = bias[col + 1];
#pragma unroll
            for (int h = 0; h < 2; h++) {
                const int rr = r + h * 8;
                float2 p;
                p.x = acc[mi][ni][2 * h + 0] + bv0;
                p.y = acc[mi][ni][2 * h + 1] + bv1;
                *(float2*)(outf + (size_t)rr * Odim + col) = p;
            }
        }
    }
}

// ---------------- host -------------------------------------------------------
static void split(const float* src, bf16* hi, bf16* lo, int n) {
    int n8 = n / 8;
    split8_kernel<<<(n8 + 255) / 256, 256>>>(
        (const float4*)src, (uint4*)hi, (uint4*)lo, n8);
}

extern "C" void kernel_launch(void* const* d_in, const int* in_sizes, int n_in,
                              void* d_out, int out_size)
{
    const float* x      = (const float*)d_in[0];
    const float* hidden = (const float*)d_in[1];
    const float* W_ih   = (const float*)d_in[3];
    const float* W_hh   = (const float*)d_in[4];
    const float* b_ih   = (const float*)d_in[5];
    const float* b_hh   = (const float*)d_in[6];
    const float* fc_W   = (const float*)d_in[7];
    const float* fc_b   = (const float*)d_in[8];
    float* out = (float*)d_out;

    bf16 *Wih_hi, *Wih_lo, *Whh_hi, *Whh_lo, *fcW_hi, *fcW_lo;
    bf16 *out_hi, *out_lo, *h0_hi, *h0_lo, *x_hi, *x_lo, *hid_hi, *hid_lo;
    cudaGetSymbolAddress((void**)&Wih_hi, g_Wih_hi);
    cudaGetSymbolAddress((void**)&Wih_lo, g_Wih_lo);
    cudaGetSymbolAddress((void**)&Whh_hi, g_Whh_hi);
    cudaGetSymbolAddress((void**)&Whh_lo, g_Whh_lo);
    cudaGetSymbolAddress((void**)&fcW_hi, g_fcW_hi);
    cudaGetSymbolAddress((void**)&fcW_lo, g_fcW_lo);
    cudaGetSymbolAddress((void**)&out_hi, g_out_hi);
    cudaGetSymbolAddress((void**)&out_lo, g_out_lo);
    cudaGetSymbolAddress((void**)&h0_hi, g_h0_hi);
    cudaGetSymbolAddress((void**)&h0_lo, g_h0_lo);
    cudaGetSymbolAddress((void**)&x_hi, g_x_hi);
    cudaGetSymbolAddress((void**)&x_lo, g_x_lo);
    cudaGetSymbolAddress((void**)&hid_hi, g_hid_hi);
    cudaGetSymbolAddress((void**)&hid_lo, g_hid_lo);

    split(W_ih, Wih_hi, Wih_lo, 2 * Hdim * Hdim);
    split(W_hh, Whh_hi, Whh_lo, 2 * Hdim * Hdim);
    split(fc_W, fcW_hi, fcW_lo, Odim * Hdim);
    split(x, x_hi, x_lo, Bdim * Hdim);
    split(hidden, hid_hi, hid_lo, 2 * Bdim * Hdim);

    constexpr int SM_RNN = 4 * 192 * RSTR;   // 110592 B
    constexpr int SM_FC  = 3 * 512 * RSTR;   // 221184 B
    cudaFuncSetAttribute(persistent_rnn,
                         cudaFuncAttributeMaxDynamicSharedMemorySize, SM_RNN);
    cudaFuncSetAttribute(fc_gemm,
                         cudaFuncAttributeMaxDynamicSharedMemorySize, SM_FC);

    persistent_rnn<<<NCTA, 256, SM_RNN>>>(
        x_hi, x_lo, hid_hi, hid_lo,
        Wih_hi, Wih_lo, Whh_hi, Whh_lo,
        b_ih, b_hh,
        out_hi, out_lo, h0_hi, h0_lo);

    const dim3 fc_grid(MTOT / 128, Odim / 128);  // (128, 64)
    fc_gemm<<<fc_grid, 256, SM_FC>>>(
        out_hi, out_lo, fcW_hi, fcW_lo, fc_b, out);
}